// round 15
// baseline (speedup 1.0000x reference)
#include <cuda_runtime.h>
#include <math.h>

// Problem constants (match reference)
#define BATCH 4
#define NPTS  300000
#define NX_   540
#define NY_   540
#define NZ_   8
#define NV_   (NX_ * NY_ * NZ_)          // 2,332,800
#define NFEAT 5

// d_out layout (tuple flattened, all float32):
//   [0, BATCH*NV_*NFEAT)   voxel means (46,656,000)
//   [.., +BATCH*NV_)       counts       (9,331,200)
//   last 3                 shape {540, 540, 8}
#define SUMS_B   (NV_ * NFEAT)           // 11,664,000 floats per batch

// z-split halves: lin is z-major, so z in [0,4) and [4,8) are contiguous
// ranges of NV_H voxels each.
#define NZ_H     (NZ_ / 2)               // 4
#define NV_H     (NX_ * NY_ * NZ_H)      // 1,166,400 voxels per half

// Scratch record padded to 32 B = exactly ONE L2 sector:
//   [x, y, z, f3 | f4, cnt, pad, pad]
// -> both reductions (v4 at +0, v2 at +16) hit the same sector (single
//    sector RMW per point, vs ~2 with the old 24B record), and the scatter
//    path is branch-free (alignment unconditional).
// Two half-batch buffers of 37.3 MB (74.6 MB total, L2-resident alongside
// the .cs streams). Zeroed at module load; fin restores zeros per dirty
// voxel (dirty <=> cnt>0), keeping the invariant across stages and replays.
#define REC 8
__device__ __align__(32) float g_scratch[2][(size_t)NV_H * REC];

#define THREADS       256
// Scatter: 1 point per thread, smem-staged (R13 shape).
#define SCAT_PTS_BLK  THREADS                                     // 256
#define SCAT_BLOCKS   ((NPTS + SCAT_PTS_BLK - 1) / SCAT_PTS_BLK)  // 1,172
#define FIN_GROUPS    (NV_H / 4)                                  // 291,600
#define FIN_BLOCKS    ((FIN_GROUPS + THREADS - 1) / THREADS)      // 1,140

// ---------------------------------------------------------------------------
__device__ __forceinline__ void red_add_v2(float* addr, float a, float b) {
    asm volatile("red.global.add.v2.f32 [%0], {%1, %2};"
                 :: "l"(addr), "f"(a), "f"(b) : "memory");
}
__device__ __forceinline__ void red_add_v4(float* addr, float a, float b,
                                           float c, float d) {
    asm volatile("red.global.add.v4.f32 [%0], {%1, %2, %3, %4};"
                 :: "l"(addr), "f"(a), "f"(b), "f"(c), "f"(d) : "memory");
}

// ---------------------------------------------------------------------------
__device__ __forceinline__ void scatter_point(float x, float y, float z,
                                              float f3, float f4,
                                              float* __restrict__ scratch,
                                              int z0) {
    // keep = all(xyz >= LO) & all(xyz <= HI), inclusive both sides
    bool keep = (x >= -54.0f) & (x <= 54.0f) &
                (y >= -54.0f) & (y <= 54.0f) &
                (z >= -5.0f)  & (z <= 3.0f);
    if (!keep) return;

    // Reference (XLA) folds /VOX into multiply by the rounded reciprocal:
    // 1/0.2f -> exactly 5.0f. Kept points have non-negative operands, so
    // truncation == floor. (Bit-exact vs reference — do not change.)
    int cz = (int)(z + 5.0f);
    cz = min(max(cz, 0), NZ_ - 1);
    if (cz < z0 || cz >= z0 + NZ_H) return;   // other half handles it

    int cx = (int)((x + 54.0f) * 5.0f);
    int cy = (int)((y + 54.0f) * 5.0f);
    cx = min(max(cx, 0), NX_ - 1);
    cy = min(max(cy, 0), NY_ - 1);

    unsigned lin = ((unsigned)(cz - z0) * NY_ + (unsigned)cy) * NX_
                 + (unsigned)cx;

    // 32B record = one sector; both ops branch-free and same-sector.
    float* r = scratch + (size_t)lin * REC;
    red_add_v4(r + 0, x, y, z, f3);
    red_add_v2(r + 4, f4, 1.0f);
}

// ---------------------------------------------------------------------------
// Fused pipeline stage, contiguous block ranges (scatter first):
//   scatter(half g)    -> g_scratch[g & 1]   (REDG path, L2-resident)
//   finalize(half g-1) -> reads g_scratch[(g-1)&1], streams dense
//                         means+counts to d_out (.cs), restores zeros
//                         per dirty voxel.
__global__ void __launch_bounds__(THREADS)
mega_kernel(const float4* __restrict__ scat_pts, int scat_buf, int scat_z0,
            unsigned n_scat,
            int fin_buf, float* __restrict__ fin_out_sums,
            float* __restrict__ fin_out_cnts,
            float* __restrict__ shape_tail) {
    __shared__ float s_pts[SCAT_PTS_BLK * NFEAT];   // 5 KB
    unsigned bid = blockIdx.x;

    if (bid < n_scat) {
        // ---- scatter: stage 256 points into smem (coalesced float4), then
        //      1 point per thread. LDS stride 5 words: gcd(5,32)=1 ->
        //      conflict-free. ----
        float* scratch = g_scratch[scat_buf];
        unsigned p0 = bid * SCAT_PTS_BLK;
        if (shape_tail != nullptr && p0 == 0 && threadIdx.x == 0) {
            shape_tail[0] = 540.0f;
            shape_tail[1] = 540.0f;
            shape_tail[2] = 8.0f;
        }
        unsigned npts_blk = min((unsigned)SCAT_PTS_BLK, (unsigned)NPTS - p0);
        unsigned nf4 = npts_blk * NFEAT / 4;   // integral (npts_blk%4==0)
        const float4* src = scat_pts + (size_t)bid * (SCAT_PTS_BLK * NFEAT / 4);
        for (unsigned i = threadIdx.x; i < nf4; i += THREADS)
            ((float4*)s_pts)[i] = __ldcs(src + i);
        __syncthreads();

        if (threadIdx.x < npts_blk) {
            const float* q = s_pts + threadIdx.x * NFEAT;
            scatter_point(q[0], q[1], q[2], q[3], q[4], scratch, scat_z0);
        }
        return;
    }
    bid -= n_scat;

    // ---- finalize: one group of 4 voxels per thread = 8 float4 reads ----
    unsigned g = bid * THREADS + threadIdx.x;
    if (g >= FIN_GROUPS) return;

    // voxel k: quad 2k = (x,y,z,f3), quad 2k+1 = (f4, cnt, pad, pad)
    float4* sr = (float4*)(g_scratch[fin_buf] + (size_t)g * 4 * REC);
    float4 a0 = sr[0], b0 = sr[1];
    float4 a1 = sr[2], b1 = sr[3];
    float4 a2 = sr[4], b2 = sr[5];
    float4 a3 = sr[6], b3 = sr[7];

    float c0 = b0.y, c1 = b1.y, c2 = b2.y, c3 = b3.y;
    float f40 = b0.x, f41 = b1.x, f42 = b2.x, f43 = b3.x;

    // mean = sum / max(cnt, 1); cnt<=1 cases are already exact passthrough.
    if (c0 > 1.5f) { a0.x = __fdiv_rn(a0.x, c0); a0.y = __fdiv_rn(a0.y, c0);
                     a0.z = __fdiv_rn(a0.z, c0); a0.w = __fdiv_rn(a0.w, c0);
                     f40 = __fdiv_rn(f40, c0); }
    if (c1 > 1.5f) { a1.x = __fdiv_rn(a1.x, c1); a1.y = __fdiv_rn(a1.y, c1);
                     a1.z = __fdiv_rn(a1.z, c1); a1.w = __fdiv_rn(a1.w, c1);
                     f41 = __fdiv_rn(f41, c1); }
    if (c2 > 1.5f) { a2.x = __fdiv_rn(a2.x, c2); a2.y = __fdiv_rn(a2.y, c2);
                     a2.z = __fdiv_rn(a2.z, c2); a2.w = __fdiv_rn(a2.w, c2);
                     f42 = __fdiv_rn(f42, c2); }
    if (c3 > 1.5f) { a3.x = __fdiv_rn(a3.x, c3); a3.y = __fdiv_rn(a3.y, c3);
                     a3.z = __fdiv_rn(a3.z, c3); a3.w = __fdiv_rn(a3.w, c3);
                     f43 = __fdiv_rn(f43, c3); }

    // Dense streaming writes to d_out (.cs keeps them out of L2 residency):
    // 4 voxels x 5 floats = 5 float4, plus 1 float4 of counts.
    float4* outs = (float4*)(fin_out_sums + (size_t)g * 20);
    __stcs(outs + 0, make_float4(a0.x, a0.y, a0.z, a0.w));
    __stcs(outs + 1, make_float4(f40,  a1.x, a1.y, a1.z));
    __stcs(outs + 2, make_float4(a1.w, f41,  a2.x, a2.y));
    __stcs(outs + 3, make_float4(a2.z, a2.w, f42,  a3.x));
    __stcs(outs + 4, make_float4(a3.y, a3.z, a3.w, f43));
    __stcs((float4*)(fin_out_cnts + (size_t)g * 4),
           make_float4(c0, c1, c2, c3));

    // Restore zeros per DIRTY voxel only (dirty <=> cnt > 0); stays in L2
    // (normal stores) for the next scatter on this buffer.
    const float4 z4 = make_float4(0.f, 0.f, 0.f, 0.f);
    if (c0 > 0.5f) { sr[0] = z4; sr[1] = z4; }
    if (c1 > 0.5f) { sr[2] = z4; sr[3] = z4; }
    if (c2 > 0.5f) { sr[4] = z4; sr[5] = z4; }
    if (c3 > 0.5f) { sr[6] = z4; sr[7] = z4; }
}

// ---------------------------------------------------------------------------
extern "C" void kernel_launch(void* const* d_in, const int* in_sizes, int n_in,
                              void* d_out, int out_size) {
    const float* pts = (const float*)d_in[0];
    float* out = (float*)d_out;

    const size_t n_sums = (size_t)BATCH * SUMS_B;        // 46,656,000
    float* sums_base = out;
    float* cnts_base = out + n_sums;
    float* shape_tail = out + n_sums + (size_t)BATCH * NV_;

    const int NHALF = BATCH * 2;   // 8 half-batches, index g = b*2 + hz

    // Pipeline: stage s runs scatter(half s) and finalize(half s-1).
    for (int s = 0; s <= NHALF; s++) {
        int g_scat = s;
        int g_fin  = s - 1;
        bool has_scat = (g_scat < NHALF);
        bool has_fin  = (g_fin >= 0);

        unsigned n_scat = has_scat ? SCAT_BLOCKS : 0;
        unsigned n_fin  = has_fin  ? FIN_BLOCKS  : 0;

        int b_scat = g_scat / 2, hz_scat = g_scat % 2;
        int b_fin  = g_fin  / 2, hz_fin  = g_fin  % 2;

        mega_kernel<<<n_scat + n_fin, THREADS>>>(
            has_scat ? (const float4*)(pts + (size_t)b_scat * NPTS * NFEAT)
                     : nullptr,
            has_scat ? (g_scat & 1) : 0,
            hz_scat * NZ_H,
            n_scat,
            has_fin ? (g_fin & 1) : 0,
            has_fin ? (sums_base + (size_t)b_fin * SUMS_B
                       + (size_t)hz_fin * NV_H * NFEAT) : nullptr,
            has_fin ? (cnts_base + (size_t)b_fin * NV_
                       + (size_t)hz_fin * NV_H) : nullptr,
            (s == 0) ? shape_tail : nullptr);
    }
}

// round 16
// speedup vs baseline: 1.0783x; 1.0783x over previous
#include <cuda_runtime.h>
#include <math.h>

// Problem constants (match reference)
#define BATCH 4
#define NPTS  300000
#define NX_   540
#define NY_   540
#define NZ_   8
#define NV_   (NX_ * NY_ * NZ_)          // 2,332,800
#define NFEAT 5

// d_out layout (tuple flattened, all float32):
//   [0, BATCH*NV_*NFEAT)   voxel means (46,656,000)
//   [.., +BATCH*NV_)       counts       (9,331,200)
//   last 3                 shape {540, 540, 8}
#define SUMS_B   (NV_ * NFEAT)           // 11,664,000 floats per batch

// z-split halves: lin is z-major, so z in [0,4) and [4,8) are contiguous
// ranges of NV_H voxels each.
#define NZ_H     (NZ_ / 2)               // 4
#define NV_H     (NX_ * NY_ * NZ_H)      // 1,166,400 voxels per half

// Scratch: 24 B record [x,y,z,f3,f4,cnt] per voxel, HALF-batch sized.
// Two buffers of 28 MB => 56 MB live in L2. Zeroed at load; finalize restores
// zeros to dirtied records (dirty <=> cnt>0), keeping the all-zeros invariant
// across stages and graph replays.
#define REC 6
__device__ __align__(16) float g_scratch[2][(size_t)NV_H * REC];

#define THREADS       256
// Scatter: 1 point per thread, smem-staged.
#define SCAT_PTS_BLK  THREADS                                     // 256
#define SCAT_BLOCKS   ((NPTS + SCAT_PTS_BLK - 1) / SCAT_PTS_BLK)  // 1,172
#define FIN_GROUPS    (NV_H / 4)                                  // 291,600
// Fin: 256 groups (1024 voxels) per block, smem-staged scratch reads.
#define FIN_GRP_BLK   THREADS                                     // 256
#define FIN_BLOCKS    ((FIN_GROUPS + FIN_GRP_BLK - 1) / FIN_GRP_BLK) // 1,140
#define FIN_TILE_F4   (FIN_GRP_BLK * REC)                         // 1,536 f4

// ---------------------------------------------------------------------------
__device__ __forceinline__ void red_add_v2(float* addr, float a, float b) {
    asm volatile("red.global.add.v2.f32 [%0], {%1, %2};"
                 :: "l"(addr), "f"(a), "f"(b) : "memory");
}
__device__ __forceinline__ void red_add_v4(float* addr, float a, float b,
                                           float c, float d) {
    asm volatile("red.global.add.v4.f32 [%0], {%1, %2, %3, %4};"
                 :: "l"(addr), "f"(a), "f"(b), "f"(c), "f"(d) : "memory");
}

// ---------------------------------------------------------------------------
__device__ __forceinline__ void scatter_point(float x, float y, float z,
                                              float f3, float f4,
                                              float* __restrict__ scratch,
                                              int z0) {
    // keep = all(xyz >= LO) & all(xyz <= HI), inclusive both sides
    bool keep = (x >= -54.0f) & (x <= 54.0f) &
                (y >= -54.0f) & (y <= 54.0f) &
                (z >= -5.0f)  & (z <= 3.0f);
    if (!keep) return;

    // Reference (XLA) folds /VOX into multiply by the rounded reciprocal:
    // 1/0.2f -> exactly 5.0f. Kept points have non-negative operands, so
    // truncation == floor. (Bit-exact vs reference — do not change.)
    int cz = (int)(z + 5.0f);
    cz = min(max(cz, 0), NZ_ - 1);
    if (cz < z0 || cz >= z0 + NZ_H) return;   // other half handles it

    int cx = (int)((x + 54.0f) * 5.0f);
    int cy = (int)((y + 54.0f) * 5.0f);
    cx = min(max(cx, 0), NX_ - 1);
    cy = min(max(cy, 0), NY_ - 1);

    unsigned lin = ((unsigned)(cz - z0) * NY_ + (unsigned)cy) * NX_
                 + (unsigned)cx;

    // Record at byte offset 24*lin: lin even -> 16B-aligned; lin odd -> r+2
    // is 16B-aligned. Both ops land in the same 24B record (usually 1 line).
    float* r = scratch + (size_t)lin * REC;
    if ((lin & 1) == 0) {
        red_add_v4(r + 0, x, y, z, f3);
        red_add_v2(r + 4, f4, 1.0f);
    } else {
        red_add_v2(r + 0, x, y);
        red_add_v4(r + 2, z, f3, f4, 1.0f);
    }
}

// ---------------------------------------------------------------------------
// Fused pipeline stage, contiguous block ranges (scatter first):
//   scatter(half g)    -> g_scratch[g & 1]   (REDG path, L2-resident)
//   finalize(half g-1) -> smem-staged coalesced reads of g_scratch[(g-1)&1],
//                         streams dense means+counts to d_out (.cs),
//                         restores zeros to dirtied records.
__global__ void __launch_bounds__(THREADS)
mega_kernel(const float4* __restrict__ scat_pts, int scat_buf, int scat_z0,
            unsigned n_scat,
            int fin_buf, float* __restrict__ fin_out_sums,
            float* __restrict__ fin_out_cnts,
            float* __restrict__ shape_tail) {
    __shared__ float  s_pts[SCAT_PTS_BLK * NFEAT];   // 5 KB  (scatter role)
    __shared__ float4 s_tile[FIN_TILE_F4];           // 24 KB (fin role)
    unsigned bid = blockIdx.x;

    if (bid < n_scat) {
        // ---- scatter: stage 256 points into smem (coalesced float4), then
        //      1 point per thread. LDS stride 5 words: gcd(5,32)=1 ->
        //      conflict-free. ----
        float* scratch = g_scratch[scat_buf];
        unsigned p0 = bid * SCAT_PTS_BLK;
        if (shape_tail != nullptr && p0 == 0 && threadIdx.x == 0) {
            shape_tail[0] = 540.0f;
            shape_tail[1] = 540.0f;
            shape_tail[2] = 8.0f;
        }
        unsigned npts_blk = min((unsigned)SCAT_PTS_BLK, (unsigned)NPTS - p0);
        unsigned nf4 = npts_blk * NFEAT / 4;   // integral (npts_blk%4==0)
        const float4* src = scat_pts + (size_t)bid * (SCAT_PTS_BLK * NFEAT / 4);
        for (unsigned i = threadIdx.x; i < nf4; i += THREADS)
            ((float4*)s_pts)[i] = __ldcs(src + i);
        __syncthreads();

        if (threadIdx.x < npts_blk) {
            const float* q = s_pts + threadIdx.x * NFEAT;
            scatter_point(q[0], q[1], q[2], q[3], q[4], scratch, scat_z0);
        }
        return;
    }
    bid -= n_scat;

    // ---- finalize: block tile of 256 groups (1024 voxels). Phase 1 stages
    //      the tile's scratch into smem with fully-coalesced float4 loads
    //      (the per-thread 96B-strided pattern costs ~3x the wavefronts and
    //      was the measured latency pole). ----
    unsigned g0 = bid * FIN_GRP_BLK;
    unsigned ngroups = min((unsigned)FIN_GRP_BLK, FIN_GROUPS - g0);
    unsigned ntile = ngroups * REC;            // float4 count for this block
    float4* srbase = (float4*)(g_scratch[fin_buf] + (size_t)g0 * 4 * REC);

    for (unsigned i = threadIdx.x; i < ntile; i += THREADS)
        s_tile[i] = srbase[i];
    __syncthreads();

    if (threadIdx.x >= ngroups) return;
    unsigned g = g0 + threadIdx.x;

    // Read this thread's group from smem (stride 24 words: ~4-way LDS
    // conflicts, cheap vs strided L2).
    float4* st = s_tile + threadIdx.x * REC;
    float4 q0 = st[0], q1 = st[1], q2 = st[2],
           q3 = st[3], q4 = st[4], q5 = st[5];

    // voxel k floats: [6k .. 6k+6) = [x,y,z,f3,f4,cnt]
    float c0 = q1.y, c1 = q2.w, c2 = q4.y, c3 = q5.w;

    float v0x = q0.x, v0y = q0.y, v0z = q0.z, v0a = q0.w, v0b = q1.x;
    float v1x = q1.z, v1y = q1.w, v1z = q2.x, v1a = q2.y, v1b = q2.z;
    float v2x = q3.x, v2y = q3.y, v2z = q3.z, v2a = q3.w, v2b = q4.x;
    float v3x = q4.z, v3y = q4.w, v3z = q5.x, v3a = q5.y, v3b = q5.z;

    // mean = sum / max(cnt, 1); cnt<=1 cases are already exact passthrough.
    if (c0 > 1.5f) { v0x = __fdiv_rn(v0x, c0); v0y = __fdiv_rn(v0y, c0);
                     v0z = __fdiv_rn(v0z, c0); v0a = __fdiv_rn(v0a, c0);
                     v0b = __fdiv_rn(v0b, c0); }
    if (c1 > 1.5f) { v1x = __fdiv_rn(v1x, c1); v1y = __fdiv_rn(v1y, c1);
                     v1z = __fdiv_rn(v1z, c1); v1a = __fdiv_rn(v1a, c1);
                     v1b = __fdiv_rn(v1b, c1); }
    if (c2 > 1.5f) { v2x = __fdiv_rn(v2x, c2); v2y = __fdiv_rn(v2y, c2);
                     v2z = __fdiv_rn(v2z, c2); v2a = __fdiv_rn(v2a, c2);
                     v2b = __fdiv_rn(v2b, c2); }
    if (c3 > 1.5f) { v3x = __fdiv_rn(v3x, c3); v3y = __fdiv_rn(v3y, c3);
                     v3z = __fdiv_rn(v3z, c3); v3a = __fdiv_rn(v3a, c3);
                     v3b = __fdiv_rn(v3b, c3); }

    // Dense streaming writes to d_out (.cs keeps them out of L2 residency):
    float4* outs = (float4*)(fin_out_sums + (size_t)g * 20);
    __stcs(outs + 0, make_float4(v0x, v0y, v0z, v0a));
    __stcs(outs + 1, make_float4(v0b, v1x, v1y, v1z));
    __stcs(outs + 2, make_float4(v1a, v1b, v2x, v2y));
    __stcs(outs + 3, make_float4(v2z, v2a, v2b, v3x));
    __stcs(outs + 4, make_float4(v3y, v3z, v3a, v3b));
    __stcs((float4*)(fin_out_cnts + (size_t)g * 4),
           make_float4(c0, c1, c2, c3));

    // Restore zeros to dirtied scratch (dirty <=> cnt > 0). Pair granularity:
    // voxels {0,1} live in quads 0..2, voxels {2,3} in quads 3..5.
    float4* sr = srbase + (size_t)threadIdx.x * REC;
    const float4 z4 = make_float4(0.f, 0.f, 0.f, 0.f);
    if (c0 > 0.5f || c1 > 0.5f) { sr[0] = z4; sr[1] = z4; sr[2] = z4; }
    if (c2 > 0.5f || c3 > 0.5f) { sr[3] = z4; sr[4] = z4; sr[5] = z4; }
}

// ---------------------------------------------------------------------------
extern "C" void kernel_launch(void* const* d_in, const int* in_sizes, int n_in,
                              void* d_out, int out_size) {
    const float* pts = (const float*)d_in[0];
    float* out = (float*)d_out;

    const size_t n_sums = (size_t)BATCH * SUMS_B;        // 46,656,000
    float* sums_base = out;
    float* cnts_base = out + n_sums;
    float* shape_tail = out + n_sums + (size_t)BATCH * NV_;

    const int NHALF = BATCH * 2;   // 8 half-batches, index g = b*2 + hz

    // Pipeline: stage s runs scatter(half s) and finalize(half s-1).
    for (int s = 0; s <= NHALF; s++) {
        int g_scat = s;
        int g_fin  = s - 1;
        bool has_scat = (g_scat < NHALF);
        bool has_fin  = (g_fin >= 0);

        unsigned n_scat = has_scat ? SCAT_BLOCKS : 0;
        unsigned n_fin  = has_fin  ? FIN_BLOCKS  : 0;

        int b_scat = g_scat / 2, hz_scat = g_scat % 2;
        int b_fin  = g_fin  / 2, hz_fin  = g_fin  % 2;

        mega_kernel<<<n_scat + n_fin, THREADS>>>(
            has_scat ? (const float4*)(pts + (size_t)b_scat * NPTS * NFEAT)
                     : nullptr,
            has_scat ? (g_scat & 1) : 0,
            hz_scat * NZ_H,
            n_scat,
            has_fin ? (g_fin & 1) : 0,
            has_fin ? (sums_base + (size_t)b_fin * SUMS_B
                       + (size_t)hz_fin * NV_H * NFEAT) : nullptr,
            has_fin ? (cnts_base + (size_t)b_fin * NV_
                       + (size_t)hz_fin * NV_H) : nullptr,
            (s == 0) ? shape_tail : nullptr);
    }
}

// round 17
// speedup vs baseline: 1.3467x; 1.2489x over previous
#include <cuda_runtime.h>
#include <math.h>

// Problem constants (match reference)
#define BATCH 4
#define NPTS  300000
#define NX_   540
#define NY_   540
#define NZ_   8
#define NV_   (NX_ * NY_ * NZ_)          // 2,332,800
#define NFEAT 5

// d_out layout (tuple flattened, all float32):
//   [0, BATCH*NV_*NFEAT)   voxel means (46,656,000)
//   [.., +BATCH*NV_)       counts       (9,331,200)
//   last 3                 shape {540, 540, 8}
#define SUMS_B   (NV_ * NFEAT)           // 11,664,000 floats per batch

// z-split halves: lin is z-major, so z in [0,4) and [4,8) are contiguous
// ranges of NV_H voxels each. Half index g = batch*2 + hz.
// Chain A = even g (hz=0, buffer 0); chain B = odd g (hz=1, buffer 1).
// The two chains share NOTHING (disjoint scratch buffers, disjoint output
// regions), so they run on two concurrent streams; within a chain, stream
// FIFO order encodes SCAT(g) -> FIN(g) -> SCAT(g+2).
#define NZ_H     (NZ_ / 2)               // 4
#define NV_H     (NX_ * NY_ * NZ_H)      // 1,166,400 voxels per half

// Scratch: 24 B record [x,y,z,f3,f4,cnt] per voxel, HALF-batch sized.
// Two buffers of 28 MB => 56 MB live in L2. Zeroed at module load; fin
// restores zeros to dirtied records (dirty <=> cnt>0), keeping the all-zeros
// invariant across stages and graph replays.
#define REC 6
__device__ __align__(16) float g_scratch[2][(size_t)NV_H * REC];

#define THREADS       256
#define SCAT_PTS_BLK  THREADS                                     // 256
#define SCAT_BLOCKS   ((NPTS + SCAT_PTS_BLK - 1) / SCAT_PTS_BLK)  // 1,172
#define FIN_GROUPS    (NV_H / 4)                                  // 291,600
#define FIN_BLOCKS    ((FIN_GROUPS + THREADS - 1) / THREADS)      // 1,140

// ---------------------------------------------------------------------------
__device__ __forceinline__ void red_add_v2(float* addr, float a, float b) {
    asm volatile("red.global.add.v2.f32 [%0], {%1, %2};"
                 :: "l"(addr), "f"(a), "f"(b) : "memory");
}
__device__ __forceinline__ void red_add_v4(float* addr, float a, float b,
                                           float c, float d) {
    asm volatile("red.global.add.v4.f32 [%0], {%1, %2, %3, %4};"
                 :: "l"(addr), "f"(a), "f"(b), "f"(c), "f"(d) : "memory");
}

// ---------------------------------------------------------------------------
__device__ __forceinline__ void scatter_point(float x, float y, float z,
                                              float f3, float f4,
                                              float* __restrict__ scratch,
                                              int z0) {
    // keep = all(xyz >= LO) & all(xyz <= HI), inclusive both sides
    bool keep = (x >= -54.0f) & (x <= 54.0f) &
                (y >= -54.0f) & (y <= 54.0f) &
                (z >= -5.0f)  & (z <= 3.0f);
    if (!keep) return;

    // Reference (XLA) folds /VOX into multiply by the rounded reciprocal:
    // 1/0.2f -> exactly 5.0f. Kept points have non-negative operands, so
    // truncation == floor. (Bit-exact vs reference — do not change.)
    int cz = (int)(z + 5.0f);
    cz = min(max(cz, 0), NZ_ - 1);
    if (cz < z0 || cz >= z0 + NZ_H) return;   // other half handles it

    int cx = (int)((x + 54.0f) * 5.0f);
    int cy = (int)((y + 54.0f) * 5.0f);
    cx = min(max(cx, 0), NX_ - 1);
    cy = min(max(cy, 0), NY_ - 1);

    unsigned lin = ((unsigned)(cz - z0) * NY_ + (unsigned)cy) * NX_
                 + (unsigned)cx;

    // Record at byte offset 24*lin: lin even -> 16B-aligned; lin odd -> r+2
    // is 16B-aligned. Both ops land in the same 24B record (usually 1 line).
    float* r = scratch + (size_t)lin * REC;
    if ((lin & 1) == 0) {
        red_add_v4(r + 0, x, y, z, f3);
        red_add_v2(r + 4, f4, 1.0f);
    } else {
        red_add_v2(r + 0, x, y);
        red_add_v4(r + 2, z, f3, f4, 1.0f);
    }
}

// ---------------------------------------------------------------------------
// Scatter: stage 256 points into smem (coalesced float4), then 1 point per
// thread. LDS stride 5 words: gcd(5,32)=1 -> conflict-free. (R13 champion.)
__global__ void __launch_bounds__(THREADS)
scat_kernel(const float4* __restrict__ pts4, int buf, int z0,
            float* __restrict__ shape_tail) {
    __shared__ float s_pts[SCAT_PTS_BLK * NFEAT];   // 5 KB
    float* scratch = g_scratch[buf];
    unsigned p0 = blockIdx.x * SCAT_PTS_BLK;
    if (shape_tail != nullptr && p0 == 0 && threadIdx.x == 0) {
        shape_tail[0] = 540.0f;
        shape_tail[1] = 540.0f;
        shape_tail[2] = 8.0f;
    }
    unsigned npts_blk = min((unsigned)SCAT_PTS_BLK, (unsigned)NPTS - p0);
    unsigned nf4 = npts_blk * NFEAT / 4;   // integral (npts_blk%4==0)
    const float4* src = pts4 + (size_t)blockIdx.x * (SCAT_PTS_BLK * NFEAT / 4);
    for (unsigned i = threadIdx.x; i < nf4; i += THREADS)
        ((float4*)s_pts)[i] = __ldcs(src + i);
    __syncthreads();

    if (threadIdx.x < npts_blk) {
        const float* q = s_pts + threadIdx.x * NFEAT;
        scatter_point(q[0], q[1], q[2], q[3], q[4], scratch, z0);
    }
}

// ---------------------------------------------------------------------------
// Fin: one group of 4 voxels per thread = 6 float4 scratch reads -> dense
// .cs output writes -> restore zeros to dirtied scratch. (R13 champion.)
__global__ void __launch_bounds__(THREADS)
fin_kernel(int buf, float* __restrict__ out_sums,
           float* __restrict__ out_cnts) {
    unsigned g = blockIdx.x * THREADS + threadIdx.x;
    if (g >= FIN_GROUPS) return;

    float4* sr = (float4*)(g_scratch[buf] + (size_t)g * 4 * REC);
    float4 q0 = sr[0], q1 = sr[1], q2 = sr[2],
           q3 = sr[3], q4 = sr[4], q5 = sr[5];

    // voxel k floats: [6k .. 6k+6) = [x,y,z,f3,f4,cnt]
    float c0 = q1.y, c1 = q2.w, c2 = q4.y, c3 = q5.w;

    float v0x = q0.x, v0y = q0.y, v0z = q0.z, v0a = q0.w, v0b = q1.x;
    float v1x = q1.z, v1y = q1.w, v1z = q2.x, v1a = q2.y, v1b = q2.z;
    float v2x = q3.x, v2y = q3.y, v2z = q3.z, v2a = q3.w, v2b = q4.x;
    float v3x = q4.z, v3y = q4.w, v3z = q5.x, v3a = q5.y, v3b = q5.z;

    // mean = sum / max(cnt, 1); cnt<=1 cases are already exact passthrough.
    if (c0 > 1.5f) { v0x = __fdiv_rn(v0x, c0); v0y = __fdiv_rn(v0y, c0);
                     v0z = __fdiv_rn(v0z, c0); v0a = __fdiv_rn(v0a, c0);
                     v0b = __fdiv_rn(v0b, c0); }
    if (c1 > 1.5f) { v1x = __fdiv_rn(v1x, c1); v1y = __fdiv_rn(v1y, c1);
                     v1z = __fdiv_rn(v1z, c1); v1a = __fdiv_rn(v1a, c1);
                     v1b = __fdiv_rn(v1b, c1); }
    if (c2 > 1.5f) { v2x = __fdiv_rn(v2x, c2); v2y = __fdiv_rn(v2y, c2);
                     v2z = __fdiv_rn(v2z, c2); v2a = __fdiv_rn(v2a, c2);
                     v2b = __fdiv_rn(v2b, c2); }
    if (c3 > 1.5f) { v3x = __fdiv_rn(v3x, c3); v3y = __fdiv_rn(v3y, c3);
                     v3z = __fdiv_rn(v3z, c3); v3a = __fdiv_rn(v3a, c3);
                     v3b = __fdiv_rn(v3b, c3); }

    // Dense streaming writes to d_out (.cs keeps them out of L2 residency):
    float4* outs = (float4*)(out_sums + (size_t)g * 20);
    __stcs(outs + 0, make_float4(v0x, v0y, v0z, v0a));
    __stcs(outs + 1, make_float4(v0b, v1x, v1y, v1z));
    __stcs(outs + 2, make_float4(v1a, v1b, v2x, v2y));
    __stcs(outs + 3, make_float4(v2z, v2a, v2b, v3x));
    __stcs(outs + 4, make_float4(v3y, v3z, v3a, v3b));
    __stcs((float4*)(out_cnts + (size_t)g * 4),
           make_float4(c0, c1, c2, c3));

    // Restore zeros to dirtied scratch (dirty <=> cnt > 0). Pair granularity:
    // voxels {0,1} live in q0..q2, voxels {2,3} in q3..q5.
    const float4 z4 = make_float4(0.f, 0.f, 0.f, 0.f);
    if (c0 > 0.5f || c1 > 0.5f) { sr[0] = z4; sr[1] = z4; sr[2] = z4; }
    if (c2 > 0.5f || c3 > 0.5f) { sr[3] = z4; sr[4] = z4; sr[5] = z4; }
}

// ---------------------------------------------------------------------------
extern "C" void kernel_launch(void* const* d_in, const int* in_sizes, int n_in,
                              void* d_out, int out_size) {
    const float* pts = (const float*)d_in[0];
    float* out = (float*)d_out;

    const size_t n_sums = (size_t)BATCH * SUMS_B;        // 46,656,000
    float* sums_base = out;
    float* cnts_base = out + n_sums;
    float* shape_tail = out + n_sums + (size_t)BATCH * NV_;

    // Two concurrent chains on two streams. Lazily created on the first
    // (non-capture) call and reused; the enqueued work is identical on every
    // call, so graph capture and replay stay deterministic. Host objects
    // only — no device allocations.
    static cudaStream_t sAB[2] = {nullptr, nullptr};
    static cudaEvent_t evFork = nullptr, evJoin[2] = {nullptr, nullptr};
    if (sAB[0] == nullptr) {
        cudaStreamCreateWithFlags(&sAB[0], cudaStreamNonBlocking);
        cudaStreamCreateWithFlags(&sAB[1], cudaStreamNonBlocking);
        cudaEventCreateWithFlags(&evFork, cudaEventDisableTiming);
        cudaEventCreateWithFlags(&evJoin[0], cudaEventDisableTiming);
        cudaEventCreateWithFlags(&evJoin[1], cudaEventDisableTiming);
    }

    // Fork from the harness's (captured) stream.
    cudaEventRecord(evFork, 0);
    cudaStreamWaitEvent(sAB[0], evFork, 0);
    cudaStreamWaitEvent(sAB[1], evFork, 0);

    // Chain c (c=0: even halves, buffer 0, z-low; c=1: odd halves, buffer 1,
    // z-high): SCAT(b,c) then FIN(b,c) for b = 0..3, in stream FIFO order.
    for (int b = 0; b < BATCH; b++) {
        for (int c = 0; c < 2; c++) {
            cudaStream_t st = sAB[c];
            const float4* pts_b =
                (const float4*)(pts + (size_t)b * NPTS * NFEAT);
            scat_kernel<<<SCAT_BLOCKS, THREADS, 0, st>>>(
                pts_b, c, c * NZ_H,
                (b == 0 && c == 0) ? shape_tail : nullptr);
            fin_kernel<<<FIN_BLOCKS, THREADS, 0, st>>>(
                c,
                sums_base + (size_t)b * SUMS_B + (size_t)c * NV_H * NFEAT,
                cnts_base + (size_t)b * NV_ + (size_t)c * NV_H);
        }
    }

    // Join both chains back into the harness's stream.
    cudaEventRecord(evJoin[0], sAB[0]);
    cudaEventRecord(evJoin[1], sAB[1]);
    cudaStreamWaitEvent(0, evJoin[0], 0);
    cudaStreamWaitEvent(0, evJoin[1], 0);
}